// round 2
// baseline (speedup 1.0000x reference)
#include <cuda_runtime.h>
#include <math.h>

// Problem geometry (fixed by the reference).
#define D_TOTAL 16384
#define H0      4096
#define BATCH   8

// Main-kernel tiling: 6 nonzero 4096x4096 W blocks, each split into
// 4 column tiles x 16 k-chunks -> 384 CTAs.
#define K_CHUNK   256
#define THREADS   256
#define COL_TILE  1024            // THREADS * 4 columns per CTA
#define N_CHUNKS  96              // 6 blocks * 16 k-chunks

// rho(s) transposed to [d][b] so staging reads one contiguous 32B row per k.
__device__ float g_rho_t[D_TOTAL * BATCH];
// Split-K partials: one exclusive writer per slot -> no atomics, deterministic.
__device__ float g_part[N_CHUNKS][BATCH][4096];

// The 6 nonzero (row-block, col-block) origins of block-tridiagonal W.
__constant__ int c_row0[6] = {4096,    0,  8192,  4096, 12288,  8192};
__constant__ int c_col0[6] = {   0, 4096,  4096,  8192,  8192, 12288};
// For output col-block cb, which partial chunks contribute: [start, start+cnt).
__constant__ int c_start[4] = {0, 16, 48, 80};
__constant__ int c_cnt[4]   = {16, 32, 32, 16};

__device__ __forceinline__ float sigmoid4(float x) {
    return 1.0f / (1.0f + expf(-4.0f * (x - 0.5f)));
}

// Packed dual-fp32 FMA (Blackwell): d = a*b + c per 32-bit half.
__device__ __forceinline__ unsigned long long ffma2(unsigned long long a,
                                                    unsigned long long b,
                                                    unsigned long long c) {
    unsigned long long d;
    asm("fma.rn.f32x2 %0, %1, %2, %3;" : "=l"(d) : "l"(a), "l"(b), "l"(c));
    return d;
}

__device__ __forceinline__ float2 u2f(unsigned long long v) {
    float2 f;
    asm("mov.b64 {%0, %1}, %2;" : "=f"(f.x), "=f"(f.y) : "l"(v));
    return f;
}

// Kernel 1: rho(s) transposed into scratch.
__global__ void prep_kernel(const float* __restrict__ s) {
    int tid = blockIdx.x * blockDim.x + threadIdx.x;   // 0 .. 131071
    int b = tid >> 14;              // / D_TOTAL
    int d = tid & (D_TOTAL - 1);
    g_rho_t[d * BATCH + b] = sigmoid4(s[tid]);
}

// Kernel 2: block-sparse skinny GEMM streaming only nonzero W blocks.
// grid.x = 384. Each thread owns 4 output columns (2 f32x2 lanes) x 8 batches.
__global__ void __launch_bounds__(THREADS)
gemv_kernel(const float* __restrict__ W) {
    // rho staged DUPLICATED: srho2[k][2b] = srho2[k][2b+1] = rho[k][b],
    // so the hot loop loads ready-made (r,r) f32x2 operands. 16 KB.
    __shared__ float srho2[K_CHUNK * 16];

    int bx = blockIdx.x;
    int wb = bx % 6;
    int t  = bx / 6;
    int ct = t & 3;                 // column tile within block
    int kc = t >> 2;                // k-chunk within block

    int row0 = c_row0[wb] + kc * K_CHUNK;
    int j0   = ct * COL_TILE + threadIdx.x * 4;          // column within block
    int jg0  = c_col0[wb] + j0;                          // global column

    // Stage: thread t duplicates the 8 rho values of k-row (row0 + t).
    {
        const float4* src = reinterpret_cast<const float4*>(
            &g_rho_t[(row0 + threadIdx.x) * BATCH]);
        float4 a = src[0];
        float4 b = src[1];
        float4* dst = reinterpret_cast<float4*>(&srho2[threadIdx.x * 16]);
        dst[0] = make_float4(a.x, a.x, a.y, a.y);
        dst[1] = make_float4(a.z, a.z, a.w, a.w);
        dst[2] = make_float4(b.x, b.x, b.y, b.y);
        dst[3] = make_float4(b.z, b.z, b.w, b.w);
    }
    __syncthreads();

    unsigned long long acc[BATCH][2];
#pragma unroll
    for (int b = 0; b < BATCH; b++) { acc[b][0] = 0ull; acc[b][1] = 0ull; }

    const float* wp = W + (size_t)row0 * D_TOTAL + jg0;

#pragma unroll 4
    for (int k = 0; k < K_CHUNK; k++) {
        // 16B of W: (w0,w1) and (w2,w3) as two f32x2 operands.
        ulonglong2 w2 = *reinterpret_cast<const ulonglong2*>(wp);
        wp += D_TOTAL;
        const ulonglong2* rp = reinterpret_cast<const ulonglong2*>(&srho2[k * 16]);
        ulonglong2 r01 = rp[0];   // (r0,r0),(r1,r1)
        ulonglong2 r23 = rp[1];
        ulonglong2 r45 = rp[2];
        ulonglong2 r67 = rp[3];
        acc[0][0] = ffma2(w2.x, r01.x, acc[0][0]); acc[0][1] = ffma2(w2.y, r01.x, acc[0][1]);
        acc[1][0] = ffma2(w2.x, r01.y, acc[1][0]); acc[1][1] = ffma2(w2.y, r01.y, acc[1][1]);
        acc[2][0] = ffma2(w2.x, r23.x, acc[2][0]); acc[2][1] = ffma2(w2.y, r23.x, acc[2][1]);
        acc[3][0] = ffma2(w2.x, r23.y, acc[3][0]); acc[3][1] = ffma2(w2.y, r23.y, acc[3][1]);
        acc[4][0] = ffma2(w2.x, r45.x, acc[4][0]); acc[4][1] = ffma2(w2.y, r45.x, acc[4][1]);
        acc[5][0] = ffma2(w2.x, r45.y, acc[5][0]); acc[5][1] = ffma2(w2.y, r45.y, acc[5][1]);
        acc[6][0] = ffma2(w2.x, r67.x, acc[6][0]); acc[6][1] = ffma2(w2.y, r67.x, acc[6][1]);
        acc[7][0] = ffma2(w2.x, r67.y, acc[7][0]); acc[7][1] = ffma2(w2.y, r67.y, acc[7][1]);
    }

    // Exclusive-writer partial store (coalesced float4 per batch).
    float* op = &g_part[wb * 16 + kc][0][j0];
#pragma unroll
    for (int b = 0; b < BATCH; b++) {
        float2 c01 = u2f(acc[b][0]);
        float2 c23 = u2f(acc[b][1]);
        *reinterpret_cast<float4*>(op + b * 4096) =
            make_float4(c01.x, c01.y, c23.x, c23.y);
    }
}

// Kernel 3: reduce partials + bias + Ux drive + rho' gate.
__global__ void finalize_kernel(const float* __restrict__ Ux,
                                const float* __restrict__ s,
                                const float* __restrict__ bias,
                                float* __restrict__ out) {
    int tid = blockIdx.x * blockDim.x + threadIdx.x;   // 0 .. 131071
    int b = tid >> 14;
    int d = tid & (D_TOTAL - 1);
    int cb = d >> 12;              // output col-block 0..3
    int jl = d & 4095;             // column within block
    int st = c_start[cb];
    int cnt = c_cnt[cb];           // 16 or 32 (both divisible by 4)

    float a0 = 0.f, a1 = 0.f, a2 = 0.f, a3 = 0.f;
    for (int c = 0; c < cnt; c += 4) {
        a0 += g_part[st + c + 0][b][jl];
        a1 += g_part[st + c + 1][b][jl];
        a2 += g_part[st + c + 2][b][jl];
        a3 += g_part[st + c + 3][b][jl];
    }
    float a = (a0 + a1) + (a2 + a3);

    a += bias[d];
    if (d < H0) a += Ux[b * H0 + d];
    float r = sigmoid4(s[tid]);
    out[tid] = a * (4.0f * r * (1.0f - r));
}

extern "C" void kernel_launch(void* const* d_in, const int* in_sizes, int n_in,
                              void* d_out, int out_size) {
    const float* Ux   = (const float*)d_in[0];   // [8, 4096]
    const float* s    = (const float*)d_in[1];   // [8, 16384]
    const float* W    = (const float*)d_in[2];   // [16384, 16384]
    const float* bias = (const float*)d_in[3];   // [1, 16384]
    float* out = (float*)d_out;                  // [8, 16384] fp32

    prep_kernel<<<(BATCH * D_TOTAL) / 256, 256>>>(s);
    gemv_kernel<<<6 * 4 * 16, THREADS>>>(W);
    finalize_kernel<<<(BATCH * D_TOTAL) / 256, 256>>>(Ux, s, bias, out);
}